// round 11
// baseline (speedup 1.0000x reference)
#include <cuda_runtime.h>
#include <cuda_bf16.h>
#include <cstdint>

// Problem constants
#define S_LEN   4096
#define DMODEL  1024
#define NHEAD   16
#define HDIM    64
#define N3      3072

// Scratch (__device__ globals per allocation-free rule)
__device__ float g_qkv[S_LEN * N3];
__device__ float g_attn[S_LEN * DMODEL];
__device__ __nv_bfloat16 g_qkvh[S_LEN * N3], g_qkvl[S_LEN * N3];
__device__ __nv_bfloat16 g_xhi[S_LEN * DMODEL], g_xlo[S_LEN * DMODEL];
__device__ __nv_bfloat16 g_ahi[S_LEN * DMODEL], g_alo[S_LEN * DMODEL];
__device__ __nv_bfloat16 g_wqh[N3 * DMODEL],   g_wql[N3 * DMODEL];
__device__ __nv_bfloat16 g_wph[DMODEL * DMODEL], g_wpl[DMODEL * DMODEL];

// ---------------------------------------------------------------------------
// PTX helpers
// ---------------------------------------------------------------------------
__device__ __forceinline__ uint32_t smem_u32(const void* p) {
    uint32_t a;
    asm("{ .reg .u64 t; cvta.to.shared.u64 t, %1; cvt.u32.u64 %0, t; }"
        : "=r"(a) : "l"(p));
    return a;
}

__device__ __forceinline__ void mma_bf16(float* c, const uint32_t* a, const uint32_t* b) {
    asm volatile(
        "mma.sync.aligned.m16n8k16.row.col.f32.bf16.bf16.f32 "
        "{%0,%1,%2,%3}, {%4,%5,%6,%7}, {%8,%9}, {%0,%1,%2,%3};"
        : "+f"(c[0]), "+f"(c[1]), "+f"(c[2]), "+f"(c[3])
        : "r"(a[0]), "r"(a[1]), "r"(a[2]), "r"(a[3]), "r"(b[0]), "r"(b[1]));
}

__device__ __forceinline__ void ldm_x4(uint32_t* r, uint32_t saddr) {
    asm volatile("ldmatrix.sync.aligned.m8n8.x4.shared.b16 {%0,%1,%2,%3}, [%4];"
                 : "=r"(r[0]), "=r"(r[1]), "=r"(r[2]), "=r"(r[3]) : "r"(saddr));
}
__device__ __forceinline__ void ldm_x4_t(uint32_t* r, uint32_t saddr) {
    asm volatile("ldmatrix.sync.aligned.m8n8.x4.trans.shared.b16 {%0,%1,%2,%3}, [%4];"
                 : "=r"(r[0]), "=r"(r[1]), "=r"(r[2]), "=r"(r[3]) : "r"(saddr));
}

// pack two fp32 into bf16x2 hi + residual lo
__device__ __forceinline__ void pack_pair(float p0, float p1, uint32_t& hi, uint32_t& lo) {
    __nv_bfloat162 h;
    h.x = __float2bfloat16(p0);
    h.y = __float2bfloat16(p1);
    hi = *reinterpret_cast<uint32_t*>(&h);
    __nv_bfloat162 l;
    l.x = __float2bfloat16(p0 - __bfloat162float(h.x));
    l.y = __float2bfloat16(p1 - __bfloat162float(h.y));
    lo = *reinterpret_cast<uint32_t*>(&l);
}

// split fp32x4 -> hi/lo bf16x2 pairs at base+idx (idx multiple of 4)
__device__ __forceinline__ void split_store4(__nv_bfloat16* bh, __nv_bfloat16* bl,
                                             int idx, float4 v) {
    __nv_bfloat162 h0; h0.x = __float2bfloat16(v.x); h0.y = __float2bfloat16(v.y);
    __nv_bfloat162 h1; h1.x = __float2bfloat16(v.z); h1.y = __float2bfloat16(v.w);
    __nv_bfloat162 l0;
    l0.x = __float2bfloat16(v.x - __bfloat162float(h0.x));
    l0.y = __float2bfloat16(v.y - __bfloat162float(h0.y));
    __nv_bfloat162 l1;
    l1.x = __float2bfloat16(v.z - __bfloat162float(h1.x));
    l1.y = __float2bfloat16(v.w - __bfloat162float(h1.y));
    *reinterpret_cast<__nv_bfloat162*>(bh + idx)     = h0;
    *reinterpret_cast<__nv_bfloat162*>(bh + idx + 2) = h1;
    *reinterpret_cast<__nv_bfloat162*>(bl + idx)     = l0;
    *reinterpret_cast<__nv_bfloat162*>(bl + idx + 2) = l1;
}

// ---------------------------------------------------------------------------
// Prep kernels (validated)
// ---------------------------------------------------------------------------
__global__ void __launch_bounds__(256)
split_kernel(const float* __restrict__ in,
             __nv_bfloat16* __restrict__ hi, __nv_bfloat16* __restrict__ lo) {
    int i = (blockIdx.x * 256 + threadIdx.x) * 4;
    float4 v = *reinterpret_cast<const float4*>(in + i);
    split_store4(hi, lo, i, v);
}

__global__ void __launch_bounds__(256)
splitT_kernel(const float* __restrict__ W,
              __nv_bfloat16* __restrict__ hiT, __nv_bfloat16* __restrict__ loT,
              int Kd, int Nd) {
    __shared__ __nv_bfloat16 th[32][33];
    __shared__ __nv_bfloat16 tl[32][33];
    int n0 = blockIdx.x * 32, k0 = blockIdx.y * 32;
    int tx = threadIdx.x, ty = threadIdx.y;
    #pragma unroll
    for (int j = 0; j < 4; j++) {
        float v = W[(size_t)(k0 + ty + 8 * j) * Nd + n0 + tx];
        __nv_bfloat16 h = __float2bfloat16(v);
        th[ty + 8 * j][tx] = h;
        tl[ty + 8 * j][tx] = __float2bfloat16(v - __bfloat162float(h));
    }
    __syncthreads();
    #pragma unroll
    for (int j = 0; j < 4; j++) {
        hiT[(size_t)(n0 + ty + 8 * j) * Kd + k0 + tx] = th[tx][ty + 8 * j];
        loT[(size_t)(n0 + ty + 8 * j) * Kd + k0 + tx] = tl[tx][ty + 8 * j];
    }
}

// ---------------------------------------------------------------------------
// bf16-split GEMM on HMMA, register-staged software pipeline.
// Smem layout / ldmatrix offsets / MMA math identical to validated R8 kernel.
// LDG for k-chunk i+1 issued before computing chunk i (hides gmem latency).
// launch_bounds(256,1): staging regs need > 128 regs/thread.
// ---------------------------------------------------------------------------
#define AS_LD 40
__global__ void __launch_bounds__(256, 1)
gemm_bf16_kernel(const __nv_bfloat16* __restrict__ Ah, const __nv_bfloat16* __restrict__ Al,
                 const __nv_bfloat16* __restrict__ Bh, const __nv_bfloat16* __restrict__ Bl,
                 const float* __restrict__ bias, float* __restrict__ C,
                 int M, int N, int K) {
    __shared__ __nv_bfloat16 Ash[128 * AS_LD];
    __shared__ __nv_bfloat16 Asl[128 * AS_LD];
    __shared__ __nv_bfloat16 Bsh[128 * AS_LD];
    __shared__ __nv_bfloat16 Bsl[128 * AS_LD];

    const int tid = threadIdx.x;
    const int wid = tid >> 5, lane = tid & 31;
    const int g = lane >> 2, q4 = lane & 3;
    const int wm = wid >> 2, wn = wid & 3;
    const int m0 = blockIdx.y * 128, n0 = blockIdx.x * 128;
    const int lrow = tid >> 1, loff = (tid & 1) * 16;

    const uint32_t a_off2 = (uint32_t)(((wm * 64) + ((lane >> 3) & 1) * 8 + (lane & 7)) * AS_LD
                                       + (lane >> 4) * 8) * 2;
    const uint32_t b_off2 = (uint32_t)(((wn * 32) + (lane >> 4) * 8 + (lane & 7)) * AS_LD
                                       + ((lane >> 3) & 1) * 8) * 2;

    const uint32_t sAh = smem_u32(Ash) + a_off2;
    const uint32_t sAl = smem_u32(Asl) + a_off2;
    const uint32_t sBh = smem_u32(Bsh) + b_off2;
    const uint32_t sBl = smem_u32(Bsl) + b_off2;

    const __nv_bfloat16* pAh = Ah + (size_t)(m0 + lrow) * K + loff;
    const __nv_bfloat16* pAl = Al + (size_t)(m0 + lrow) * K + loff;
    const __nv_bfloat16* pBh = Bh + (size_t)(n0 + lrow) * K + loff;
    const __nv_bfloat16* pBl = Bl + (size_t)(n0 + lrow) * K + loff;

    float Cf[4][4][4];
    #pragma unroll
    for (int mt = 0; mt < 4; mt++)
        #pragma unroll
        for (int nt = 0; nt < 4; nt++)
            #pragma unroll
            for (int e = 0; e < 4; e++) Cf[mt][nt][e] = 0.0f;

    // register staging for the next k-chunk (8 x uint4)
    uint4 rAh0, rAh1, rAl0, rAl1, rBh0, rBh1, rBl0, rBl1;
    {
        rAh0 = *reinterpret_cast<const uint4*>(pAh);
        rAh1 = *reinterpret_cast<const uint4*>(pAh + 8);
        rAl0 = *reinterpret_cast<const uint4*>(pAl);
        rAl1 = *reinterpret_cast<const uint4*>(pAl + 8);
        rBh0 = *reinterpret_cast<const uint4*>(pBh);
        rBh1 = *reinterpret_cast<const uint4*>(pBh + 8);
        rBl0 = *reinterpret_cast<const uint4*>(pBl);
        rBl1 = *reinterpret_cast<const uint4*>(pBl + 8);
    }

    for (int k0 = 0; k0 < K; k0 += 32) {
        __syncthreads();   // previous compute done reading smem
        *reinterpret_cast<uint4*>(&Ash[lrow * AS_LD + loff])     = rAh0;
        *reinterpret_cast<uint4*>(&Ash[lrow * AS_LD + loff + 8]) = rAh1;
        *reinterpret_cast<uint4*>(&Asl[lrow * AS_LD + loff])     = rAl0;
        *reinterpret_cast<uint4*>(&Asl[lrow * AS_LD + loff + 8]) = rAl1;
        *reinterpret_cast<uint4*>(&Bsh[lrow * AS_LD + loff])     = rBh0;
        *reinterpret_cast<uint4*>(&Bsh[lrow * AS_LD + loff + 8]) = rBh1;
        *reinterpret_cast<uint4*>(&Bsl[lrow * AS_LD + loff])     = rBl0;
        *reinterpret_cast<uint4*>(&Bsl[lrow * AS_LD + loff + 8]) = rBl1;
        __syncthreads();

        // issue next chunk's loads; latency hides behind the MMAs below
        if (k0 + 32 < K) {
            int kn = k0 + 32;
            rAh0 = *reinterpret_cast<const uint4*>(pAh + kn);
            rAh1 = *reinterpret_cast<const uint4*>(pAh + kn + 8);
            rAl0 = *reinterpret_cast<const uint4*>(pAl + kn);
            rAl1 = *reinterpret_cast<const uint4*>(pAl + kn + 8);
            rBh0 = *reinterpret_cast<const uint4*>(pBh + kn);
            rBh1 = *reinterpret_cast<const uint4*>(pBh + kn + 8);
            rBl0 = *reinterpret_cast<const uint4*>(pBl + kn);
            rBl1 = *reinterpret_cast<const uint4*>(pBl + kn + 8);
        }

        #pragma unroll
        for (int ks = 0; ks < 2; ks++) {
            uint32_t bh4[2][4], bl4[2][4];
            #pragma unroll
            for (int ntp = 0; ntp < 2; ntp++) {
                ldm_x4(bh4[ntp], sBh + ntp * 1280 + ks * 32);
                ldm_x4(bl4[ntp], sBl + ntp * 1280 + ks * 32);
            }
            #pragma unroll
            for (int mt = 0; mt < 4; mt++) {
                uint32_t ah4[4], al4[4];
                ldm_x4(ah4, sAh + mt * 1280 + ks * 32);
                ldm_x4(al4, sAl + mt * 1280 + ks * 32);
                #pragma unroll
                for (int ntp = 0; ntp < 2; ntp++) {
                    mma_bf16(Cf[mt][2 * ntp],     ah4, &bh4[ntp][0]);
                    mma_bf16(Cf[mt][2 * ntp],     ah4, &bl4[ntp][0]);
                    mma_bf16(Cf[mt][2 * ntp],     al4, &bh4[ntp][0]);
                    mma_bf16(Cf[mt][2 * ntp + 1], ah4, &bh4[ntp][2]);
                    mma_bf16(Cf[mt][2 * ntp + 1], ah4, &bl4[ntp][2]);
                    mma_bf16(Cf[mt][2 * ntp + 1], al4, &bh4[ntp][2]);
                }
            }
        }
    }

    #pragma unroll
    for (int mt = 0; mt < 4; mt++) {
        int row = m0 + wm * 64 + mt * 16 + g;
        #pragma unroll
        for (int nt = 0; nt < 4; nt++) {
            int col = n0 + wn * 32 + nt * 8 + 2 * q4;
            float2 b2 = *reinterpret_cast<const float2*>(bias + col);
            float2 o0 = {Cf[mt][nt][0] + b2.x, Cf[mt][nt][1] + b2.y};
            float2 o1 = {Cf[mt][nt][2] + b2.x, Cf[mt][nt][3] + b2.y};
            *reinterpret_cast<float2*>(C + (size_t)row * N + col) = o0;
            *reinterpret_cast<float2*>(C + (size_t)(row + 8) * N + col) = o1;
        }
    }
}

// ---------------------------------------------------------------------------
// Flash attention, bf16-split HMMA + ldmatrix (R10 verbatim — validated).
// ---------------------------------------------------------------------------
#define FLD 72
#define OQH 0
#define OQL (128 * FLD)
#define OKH (2 * 128 * FLD)
#define OKL (OKH + 64 * FLD)
#define OVH (OKL + 64 * FLD)
#define OVL (OVH + 64 * FLD)
#define FLASH_SMEM ((OVL + 64 * FLD) * 2)   // 73728 B

__global__ void __launch_bounds__(256, 2)
flash_bf16_kernel(const __nv_bfloat16* __restrict__ qh_g,
                  const __nv_bfloat16* __restrict__ ql_g,
                  float* __restrict__ outp) {
    extern __shared__ __nv_bfloat16 smf[];
    const uint32_t sb = smem_u32(smf);

    const int qb = (S_LEN / 128 - 1) - blockIdx.x;   // heavy tiles first
    const int h  = blockIdx.y;
    const int tid = threadIdx.x;
    const int wid = tid >> 5, lane = tid & 31;
    const int g = lane >> 2, q4 = lane & 3;
    const int qcol = h * HDIM;
    const float scale = 0.125f;

    const uint32_t qoff2 = (uint32_t)(((wid * 16) + ((lane >> 3) & 1) * 8 + (lane & 7)) * FLD
                                      + (lane >> 4) * 8) * 2;
    const uint32_t koff2 = (uint32_t)(((lane >> 4) * 8 + (lane & 7)) * FLD
                                      + ((lane >> 3) & 1) * 8) * 2;
    const uint32_t voff2 = (uint32_t)((((lane >> 3) & 1) * 8 + (lane & 7)) * FLD
                                      + (lane >> 4) * 8) * 2;

    #pragma unroll
    for (int i = 0; i < 4; i++) {
        int p = tid + i * 256;
        int r = p >> 3, c8 = (p & 7) * 8;
        size_t src = (size_t)(qb * 128 + r) * N3 + qcol + c8;
        *reinterpret_cast<uint4*>(&smf[OQH + r * FLD + c8]) =
            *reinterpret_cast<const uint4*>(qh_g + src);
        *reinterpret_cast<uint4*>(&smf[OQL + r * FLD + c8]) =
            *reinterpret_cast<const uint4*>(ql_g + src);
    }

    float O[8][4];
    #pragma unroll
    for (int nt = 0; nt < 8; nt++)
        #pragma unroll
        for (int e = 0; e < 4; e++) O[nt][e] = 0.0f;
    float m0r = -1e30f, m1r = -1e30f, l0r = 0.0f, l1r = 0.0f;

    const uint32_t qbh = sb + OQH * 2 + qoff2;
    const uint32_t qbl = sb + OQL * 2 + qoff2;
    const uint32_t kbh = sb + OKH * 2 + koff2;
    const uint32_t kbl = sb + OKL * 2 + koff2;
    const uint32_t vbh = sb + OVH * 2 + voff2;
    const uint32_t vbl = sb + OVL * 2 + voff2;

    const int nkt = 2 * qb + 2;
    for (int kb = 0; kb < nkt; kb++) {
        __syncthreads();
        #pragma unroll
        for (int i = 0; i < 2; i++) {
            int p = tid + i * 256;
            int r = p >> 3, c8 = (p & 7) * 8;
            size_t ksrc = (size_t)(kb * 64 + r) * N3 + DMODEL + qcol + c8;
            size_t vsrc = ksrc + DMODEL;
            *reinterpret_cast<uint4*>(&smf[OKH + r * FLD + c8]) =
                *reinterpret_cast<const uint4*>(qh_g + ksrc);
            *reinterpret_cast<uint4*>(&smf[OKL + r * FLD + c8]) =
                *reinterpret_cast<const uint4*>(ql_g + ksrc);
            *reinterpret_cast<uint4*>(&smf[OVH + r * FLD + c8]) =
                *reinterpret_cast<const uint4*>(qh_g + vsrc);
            *reinterpret_cast<uint4*>(&smf[OVL + r * FLD + c8]) =
                *reinterpret_cast<const uint4*>(ql_g + vsrc);
        }
        __syncthreads();

        float S[8][4];
        #pragma unroll
        for (int nt = 0; nt < 8; nt++)
            #pragma unroll
            for (int e = 0; e < 4; e++) S[nt][e] = 0.0f;

        #pragma unroll
        for (int ks = 0; ks < 4; ks++) {
            uint32_t qh4[4], ql4[4];
            ldm_x4(qh4, qbh + ks * 32);
            ldm_x4(ql4, qbl + ks * 32);
            #pragma unroll
            for (int ntp = 0; ntp < 4; ntp++) {
                uint32_t kh4[4], kl4[4];
                ldm_x4(kh4, kbh + ntp * 2304 + ks * 32);
                ldm_x4(kl4, kbl + ntp * 2304 + ks * 32);
                mma_bf16(S[2 * ntp],     qh4, &kh4[0]);
                mma_bf16(S[2 * ntp],     qh4, &kl4[0]);
                mma_bf16(S[2 * ntp],     ql4, &kh4[0]);
                mma_bf16(S[2 * ntp + 1], qh4, &kh4[2]);
                mma_bf16(S[2 * ntp + 1], qh4, &kl4[2]);
                mma_bf16(S[2 * ntp + 1], ql4, &kh4[2]);
            }
        }

        #pragma unroll
        for (int nt = 0; nt < 8; nt++) {
            S[nt][0] *= scale; S[nt][1] *= scale;
            S[nt][2] *= scale; S[nt][3] *= scale;
        }
        if (kb >= 2 * qb) {
            int row0 = qb * 128 + wid * 16 + g;
            int row1 = row0 + 8;
            #pragma unroll
            for (int nt = 0; nt < 8; nt++) {
                int c = kb * 64 + nt * 8 + 2 * q4;
                if (c     > row0) S[nt][0] = -1e30f;
                if (c + 1 > row0) S[nt][1] = -1e30f;
                if (c     > row1) S[nt][2] = -1e30f;
                if (c + 1 > row1) S[nt][3] = -1e30f;
            }
        }

        float mx0 = -1e30f, mx1 = -1e30f;
        #pragma unroll
        for (int nt = 0; nt < 8; nt++) {
            mx0 = fmaxf(mx0, fmaxf(S[nt][0], S[nt][1]));
            mx1 = fmaxf(mx1, fmaxf(S[nt][2], S[nt][3]));
        }
        mx0 = fmaxf(mx0, __shfl_xor_sync(0xffffffffu, mx0, 1));
        mx0 = fmaxf(mx0, __shfl_xor_sync(0xffffffffu, mx0, 2));
        mx1 = fmaxf(mx1, __shfl_xor_sync(0xffffffffu, mx1, 1));
        mx1 = fmaxf(mx1, __shfl_xor_sync(0xffffffffu, mx1, 2));
        float mn0 = fmaxf(m0r, mx0), mn1 = fmaxf(m1r, mx1);
        float al0 = __expf(m0r - mn0), al1 = __expf(m1r - mn1);
        float rs0 = 0.0f, rs1 = 0.0f;
        #pragma unroll
        for (int nt = 0; nt < 8; nt++) {
            S[nt][0] = __expf(S[nt][0] - mn0);
            S[nt][1] = __expf(S[nt][1] - mn0);
            S[nt][2] = __expf(S[nt][2] - mn1);
            S[nt][3] = __expf(S[nt][3] - mn1);
            rs0 += S[nt][0] + S[nt][1];
            rs1 += S[nt][2] + S[nt][3];
        }
        rs0 += __shfl_xor_sync(0xffffffffu, rs0, 1);
        rs0 += __shfl_xor_sync(0xffffffffu, rs0, 2);
        rs1 += __shfl_xor_sync(0xffffffffu, rs1, 1);
        rs1 += __shfl_xor_sync(0xffffffffu, rs1, 2);
        l0r = l0r * al0 + rs0;
        l1r = l1r * al1 + rs1;
        m0r = mn0; m1r = mn1;
        #pragma unroll
        for (int nt = 0; nt < 8; nt++) {
            O[nt][0] *= al0; O[nt][1] *= al0;
            O[nt][2] *= al1; O[nt][3] *= al1;
        }

        #pragma unroll
        for (int ks = 0; ks < 4; ks++) {
            uint32_t ph[4], pl[4];
            pack_pair(S[2 * ks][0],     S[2 * ks][1],     ph[0], pl[0]);
            pack_pair(S[2 * ks][2],     S[2 * ks][3],     ph[1], pl[1]);
            pack_pair(S[2 * ks + 1][0], S[2 * ks + 1][1], ph[2], pl[2]);
            pack_pair(S[2 * ks + 1][2], S[2 * ks + 1][3], ph[3], pl[3]);
            #pragma unroll
            for (int ntp = 0; ntp < 4; ntp++) {
                uint32_t vh4[4], vl4[4];
                ldm_x4_t(vh4, vbh + ks * 2304 + ntp * 32);
                ldm_x4_t(vl4, vbl + ks * 2304 + ntp * 32);
                mma_bf16(O[2 * ntp],     ph, &vh4[0]);
                mma_bf16(O[2 * ntp],     ph, &vl4[0]);
                mma_bf16(O[2 * ntp],     pl, &vh4[0]);
                mma_bf16(O[2 * ntp + 1], ph, &vh4[2]);
                mma_bf16(O[2 * ntp + 1], ph, &vl4[2]);
                mma_bf16(O[2 * ntp + 1], pl, &vh4[2]);
            }
        }
    }

    float inv0 = 1.0f / l0r, inv1 = 1.0f / l1r;
    int row0 = qb * 128 + wid * 16 + g;
    int row1 = row0 + 8;
    #pragma unroll
    for (int nt = 0; nt < 8; nt++) {
        int col = qcol + nt * 8 + 2 * q4;
        float2 o0 = {O[nt][0] * inv0, O[nt][1] * inv0};
        float2 o1 = {O[nt][2] * inv1, O[nt][3] * inv1};
        *reinterpret_cast<float2*>(outp + (size_t)row0 * DMODEL + col) = o0;
        *reinterpret_cast<float2*>(outp + (size_t)row1 * DMODEL + col) = o1;
    }
}

// ---------------------------------------------------------------------------
// Launch
// ---------------------------------------------------------------------------
extern "C" void kernel_launch(void* const* d_in, const int* in_sizes, int n_in,
                              void* d_out, int out_size) {
    const float* x      = (const float*)d_in[0];
    const float* w_qkv  = (const float*)d_in[1];
    const float* b_qkv  = (const float*)d_in[2];
    const float* w_proj = (const float*)d_in[3];
    const float* b_proj = (const float*)d_in[4];
    float* out = (float*)d_out;

    float *qkv, *attn;
    __nv_bfloat16 *qkvh, *qkvl, *xhi, *xlo, *ahi, *alo, *wqh, *wql, *wph, *wpl;
    cudaGetSymbolAddress((void**)&qkv, g_qkv);
    cudaGetSymbolAddress((void**)&attn, g_attn);
    cudaGetSymbolAddress((void**)&qkvh, g_qkvh);
    cudaGetSymbolAddress((void**)&qkvl, g_qkvl);
    cudaGetSymbolAddress((void**)&xhi, g_xhi);
    cudaGetSymbolAddress((void**)&xlo, g_xlo);
    cudaGetSymbolAddress((void**)&ahi, g_ahi);
    cudaGetSymbolAddress((void**)&alo, g_alo);
    cudaGetSymbolAddress((void**)&wqh, g_wqh);
    cudaGetSymbolAddress((void**)&wql, g_wql);
    cudaGetSymbolAddress((void**)&wph, g_wph);
    cudaGetSymbolAddress((void**)&wpl, g_wpl);

    cudaFuncSetAttribute(flash_bf16_kernel,
                         cudaFuncAttributeMaxDynamicSharedMemorySize, FLASH_SMEM);

    // Prep: split x; split+transpose weights
    split_kernel<<<S_LEN * DMODEL / 1024, 256>>>(x, xhi, xlo);
    splitT_kernel<<<dim3(N3 / 32, DMODEL / 32), dim3(32, 8)>>>(w_qkv, wqh, wql, DMODEL, N3);
    splitT_kernel<<<dim3(DMODEL / 32, DMODEL / 32), dim3(32, 8)>>>(w_proj, wph, wpl, DMODEL, DMODEL);

    // 1) QKV projection (pipelined GEMM, fp32 out)
    gemm_bf16_kernel<<<dim3(N3 / 128, S_LEN / 128), 256>>>(
        xhi, xlo, wqh, wql, b_qkv, qkv, S_LEN, N3, DMODEL);

    // 1b) Split qkv to bf16 hi/lo once
    split_kernel<<<S_LEN * N3 / 1024, 256>>>(qkv, qkvh, qkvl);

    // 2) Causal flash attention (reads pre-split bf16)
    flash_bf16_kernel<<<dim3(S_LEN / 128, NHEAD), 256, FLASH_SMEM>>>(qkvh, qkvl, attn);

    // 3) Output projection
    split_kernel<<<S_LEN * DMODEL / 1024, 256>>>(attn, ahi, alo);
    gemm_bf16_kernel<<<dim3(DMODEL / 128, S_LEN / 128), 256>>>(
        ahi, alo, wph, wpl, b_proj, out, S_LEN, DMODEL, DMODEL);
}

// round 12
// speedup vs baseline: 1.5816x; 1.5816x over previous
#include <cuda_runtime.h>
#include <cuda_bf16.h>
#include <cstdint>

// Problem constants
#define S_LEN   4096
#define DMODEL  1024
#define NHEAD   16
#define HDIM    64
#define N3      3072

// Scratch (__device__ globals per allocation-free rule)
__device__ float g_qkv[S_LEN * N3];
__device__ float g_attn[S_LEN * DMODEL];
__device__ __nv_bfloat16 g_qkvh[S_LEN * N3], g_qkvl[S_LEN * N3];
__device__ __nv_bfloat16 g_xhi[S_LEN * DMODEL], g_xlo[S_LEN * DMODEL];
__device__ __nv_bfloat16 g_ahi[S_LEN * DMODEL], g_alo[S_LEN * DMODEL];
__device__ __nv_bfloat16 g_wqh[N3 * DMODEL],   g_wql[N3 * DMODEL];
__device__ __nv_bfloat16 g_wph[DMODEL * DMODEL], g_wpl[DMODEL * DMODEL];

// ---------------------------------------------------------------------------
// PTX helpers
// ---------------------------------------------------------------------------
__device__ __forceinline__ uint32_t smem_u32(const void* p) {
    uint32_t a;
    asm("{ .reg .u64 t; cvta.to.shared.u64 t, %1; cvt.u32.u64 %0, t; }"
        : "=r"(a) : "l"(p));
    return a;
}

__device__ __forceinline__ void mma_bf16(float* c, const uint32_t* a, const uint32_t* b) {
    asm volatile(
        "mma.sync.aligned.m16n8k16.row.col.f32.bf16.bf16.f32 "
        "{%0,%1,%2,%3}, {%4,%5,%6,%7}, {%8,%9}, {%0,%1,%2,%3};"
        : "+f"(c[0]), "+f"(c[1]), "+f"(c[2]), "+f"(c[3])
        : "r"(a[0]), "r"(a[1]), "r"(a[2]), "r"(a[3]), "r"(b[0]), "r"(b[1]));
}

__device__ __forceinline__ void ldm_x4(uint32_t* r, uint32_t saddr) {
    asm volatile("ldmatrix.sync.aligned.m8n8.x4.shared.b16 {%0,%1,%2,%3}, [%4];"
                 : "=r"(r[0]), "=r"(r[1]), "=r"(r[2]), "=r"(r[3]) : "r"(saddr));
}
__device__ __forceinline__ void ldm_x4_t(uint32_t* r, uint32_t saddr) {
    asm volatile("ldmatrix.sync.aligned.m8n8.x4.trans.shared.b16 {%0,%1,%2,%3}, [%4];"
                 : "=r"(r[0]), "=r"(r[1]), "=r"(r[2]), "=r"(r[3]) : "r"(saddr));
}

// pack two fp32 into bf16x2 hi + residual lo
__device__ __forceinline__ void pack_pair(float p0, float p1, uint32_t& hi, uint32_t& lo) {
    __nv_bfloat162 h;
    h.x = __float2bfloat16(p0);
    h.y = __float2bfloat16(p1);
    hi = *reinterpret_cast<uint32_t*>(&h);
    __nv_bfloat162 l;
    l.x = __float2bfloat16(p0 - __bfloat162float(h.x));
    l.y = __float2bfloat16(p1 - __bfloat162float(h.y));
    lo = *reinterpret_cast<uint32_t*>(&l);
}

// split fp32x4 -> hi/lo bf16x2 pairs at base+idx (idx multiple of 4)
__device__ __forceinline__ void split_store4(__nv_bfloat16* bh, __nv_bfloat16* bl,
                                             int idx, float4 v) {
    __nv_bfloat162 h0; h0.x = __float2bfloat16(v.x); h0.y = __float2bfloat16(v.y);
    __nv_bfloat162 h1; h1.x = __float2bfloat16(v.z); h1.y = __float2bfloat16(v.w);
    __nv_bfloat162 l0;
    l0.x = __float2bfloat16(v.x - __bfloat162float(h0.x));
    l0.y = __float2bfloat16(v.y - __bfloat162float(h0.y));
    __nv_bfloat162 l1;
    l1.x = __float2bfloat16(v.z - __bfloat162float(h1.x));
    l1.y = __float2bfloat16(v.w - __bfloat162float(h1.y));
    *reinterpret_cast<__nv_bfloat162*>(bh + idx)     = h0;
    *reinterpret_cast<__nv_bfloat162*>(bh + idx + 2) = h1;
    *reinterpret_cast<__nv_bfloat162*>(bl + idx)     = l0;
    *reinterpret_cast<__nv_bfloat162*>(bl + idx + 2) = l1;
}

// ---------------------------------------------------------------------------
// Prep kernels (validated)
// ---------------------------------------------------------------------------
__global__ void __launch_bounds__(256)
split_kernel(const float* __restrict__ in,
             __nv_bfloat16* __restrict__ hi, __nv_bfloat16* __restrict__ lo) {
    int i = (blockIdx.x * 256 + threadIdx.x) * 4;
    float4 v = *reinterpret_cast<const float4*>(in + i);
    split_store4(hi, lo, i, v);
}

__global__ void __launch_bounds__(256)
splitT_kernel(const float* __restrict__ W,
              __nv_bfloat16* __restrict__ hiT, __nv_bfloat16* __restrict__ loT,
              int Kd, int Nd) {
    __shared__ __nv_bfloat16 th[32][33];
    __shared__ __nv_bfloat16 tl[32][33];
    int n0 = blockIdx.x * 32, k0 = blockIdx.y * 32;
    int tx = threadIdx.x, ty = threadIdx.y;
    #pragma unroll
    for (int j = 0; j < 4; j++) {
        float v = W[(size_t)(k0 + ty + 8 * j) * Nd + n0 + tx];
        __nv_bfloat16 h = __float2bfloat16(v);
        th[ty + 8 * j][tx] = h;
        tl[ty + 8 * j][tx] = __float2bfloat16(v - __bfloat162float(h));
    }
    __syncthreads();
    #pragma unroll
    for (int j = 0; j < 4; j++) {
        hiT[(size_t)(n0 + ty + 8 * j) * Kd + k0 + tx] = th[tx][ty + 8 * j];
        loT[(size_t)(n0 + ty + 8 * j) * Kd + k0 + tx] = tl[tx][ty + 8 * j];
    }
}

// ---------------------------------------------------------------------------
// bf16-split GEMM on HMMA. R8 skeleton (2 CTAs/SM, sync loads) with MMAs
// reordered for accumulator independence (revisit distance 4 instead of 1).
// Per-accumulator term order unchanged (hh, hl, lh) -> bit-identical results.
// ---------------------------------------------------------------------------
#define AS_LD 40
__global__ void __launch_bounds__(256, 2)
gemm_bf16_kernel(const __nv_bfloat16* __restrict__ Ah, const __nv_bfloat16* __restrict__ Al,
                 const __nv_bfloat16* __restrict__ Bh, const __nv_bfloat16* __restrict__ Bl,
                 const float* __restrict__ bias, float* __restrict__ C,
                 int M, int N, int K) {
    __shared__ __nv_bfloat16 Ash[128 * AS_LD];
    __shared__ __nv_bfloat16 Asl[128 * AS_LD];
    __shared__ __nv_bfloat16 Bsh[128 * AS_LD];
    __shared__ __nv_bfloat16 Bsl[128 * AS_LD];

    const int tid = threadIdx.x;
    const int wid = tid >> 5, lane = tid & 31;
    const int g = lane >> 2, q4 = lane & 3;
    const int wm = wid >> 2, wn = wid & 3;
    const int m0 = blockIdx.y * 128, n0 = blockIdx.x * 128;
    const int lrow = tid >> 1, loff = (tid & 1) * 16;

    const uint32_t a_off2 = (uint32_t)(((wm * 64) + ((lane >> 3) & 1) * 8 + (lane & 7)) * AS_LD
                                       + (lane >> 4) * 8) * 2;
    const uint32_t b_off2 = (uint32_t)(((wn * 32) + (lane >> 4) * 8 + (lane & 7)) * AS_LD
                                       + ((lane >> 3) & 1) * 8) * 2;

    const uint32_t sAh = smem_u32(Ash) + a_off2;
    const uint32_t sAl = smem_u32(Asl) + a_off2;
    const uint32_t sBh = smem_u32(Bsh) + b_off2;
    const uint32_t sBl = smem_u32(Bsl) + b_off2;

    float Cf[4][4][4];
    #pragma unroll
    for (int mt = 0; mt < 4; mt++)
        #pragma unroll
        for (int nt = 0; nt < 4; nt++)
            #pragma unroll
            for (int e = 0; e < 4; e++) Cf[mt][nt][e] = 0.0f;

    for (int k0 = 0; k0 < K; k0 += 32) {
        __syncthreads();
        {
            const __nv_bfloat16* pa = Ah + (size_t)(m0 + lrow) * K + k0 + loff;
            *reinterpret_cast<uint4*>(&Ash[lrow * AS_LD + loff])     = *reinterpret_cast<const uint4*>(pa);
            *reinterpret_cast<uint4*>(&Ash[lrow * AS_LD + loff + 8]) = *reinterpret_cast<const uint4*>(pa + 8);
            const __nv_bfloat16* pl = Al + (size_t)(m0 + lrow) * K + k0 + loff;
            *reinterpret_cast<uint4*>(&Asl[lrow * AS_LD + loff])     = *reinterpret_cast<const uint4*>(pl);
            *reinterpret_cast<uint4*>(&Asl[lrow * AS_LD + loff + 8]) = *reinterpret_cast<const uint4*>(pl + 8);
            const __nv_bfloat16* pb = Bh + (size_t)(n0 + lrow) * K + k0 + loff;
            *reinterpret_cast<uint4*>(&Bsh[lrow * AS_LD + loff])     = *reinterpret_cast<const uint4*>(pb);
            *reinterpret_cast<uint4*>(&Bsh[lrow * AS_LD + loff + 8]) = *reinterpret_cast<const uint4*>(pb + 8);
            const __nv_bfloat16* pc = Bl + (size_t)(n0 + lrow) * K + k0 + loff;
            *reinterpret_cast<uint4*>(&Bsl[lrow * AS_LD + loff])     = *reinterpret_cast<const uint4*>(pc);
            *reinterpret_cast<uint4*>(&Bsl[lrow * AS_LD + loff + 8]) = *reinterpret_cast<const uint4*>(pc + 8);
        }
        __syncthreads();

        #pragma unroll
        for (int ks = 0; ks < 2; ks++) {
            uint32_t bh4[2][4], bl4[2][4];
            #pragma unroll
            for (int ntp = 0; ntp < 2; ntp++) {
                ldm_x4(bh4[ntp], sBh + ntp * 1280 + ks * 32);
                ldm_x4(bl4[ntp], sBl + ntp * 1280 + ks * 32);
            }
            #pragma unroll
            for (int mt = 0; mt < 4; mt++) {
                uint32_t ah4[4], al4[4];
                ldm_x4(ah4, sAh + mt * 1280 + ks * 32);
                ldm_x4(al4, sAl + mt * 1280 + ks * 32);
                // pass 1 (hh): 4 distinct accumulators
                mma_bf16(Cf[mt][0], ah4, &bh4[0][0]);
                mma_bf16(Cf[mt][1], ah4, &bh4[0][2]);
                mma_bf16(Cf[mt][2], ah4, &bh4[1][0]);
                mma_bf16(Cf[mt][3], ah4, &bh4[1][2]);
                // pass 2 (hl)
                mma_bf16(Cf[mt][0], ah4, &bl4[0][0]);
                mma_bf16(Cf[mt][1], ah4, &bl4[0][2]);
                mma_bf16(Cf[mt][2], ah4, &bl4[1][0]);
                mma_bf16(Cf[mt][3], ah4, &bl4[1][2]);
                // pass 3 (lh)
                mma_bf16(Cf[mt][0], al4, &bh4[0][0]);
                mma_bf16(Cf[mt][1], al4, &bh4[0][2]);
                mma_bf16(Cf[mt][2], al4, &bh4[1][0]);
                mma_bf16(Cf[mt][3], al4, &bh4[1][2]);
            }
        }
    }

    #pragma unroll
    for (int mt = 0; mt < 4; mt++) {
        int row = m0 + wm * 64 + mt * 16 + g;
        #pragma unroll
        for (int nt = 0; nt < 4; nt++) {
            int col = n0 + wn * 32 + nt * 8 + 2 * q4;
            float2 b2 = *reinterpret_cast<const float2*>(bias + col);
            float2 o0 = {Cf[mt][nt][0] + b2.x, Cf[mt][nt][1] + b2.y};
            float2 o1 = {Cf[mt][nt][2] + b2.x, Cf[mt][nt][3] + b2.y};
            *reinterpret_cast<float2*>(C + (size_t)row * N + col) = o0;
            *reinterpret_cast<float2*>(C + (size_t)(row + 8) * N + col) = o1;
        }
    }
}

// ---------------------------------------------------------------------------
// Flash attention, bf16-split HMMA + ldmatrix. Br=128, Bc=64.
// MMAs interleaved across the two accumulators per ntp (distance 2).
// ---------------------------------------------------------------------------
#define FLD 72
#define OQH 0
#define OQL (128 * FLD)
#define OKH (2 * 128 * FLD)
#define OKL (OKH + 64 * FLD)
#define OVH (OKL + 64 * FLD)
#define OVL (OVH + 64 * FLD)
#define FLASH_SMEM ((OVL + 64 * FLD) * 2)   // 73728 B

__global__ void __launch_bounds__(256, 2)
flash_bf16_kernel(const __nv_bfloat16* __restrict__ qh_g,
                  const __nv_bfloat16* __restrict__ ql_g,
                  float* __restrict__ outp) {
    extern __shared__ __nv_bfloat16 smf[];
    const uint32_t sb = smem_u32(smf);

    const int qb = (S_LEN / 128 - 1) - blockIdx.x;   // heavy tiles first
    const int h  = blockIdx.y;
    const int tid = threadIdx.x;
    const int wid = tid >> 5, lane = tid & 31;
    const int g = lane >> 2, q4 = lane & 3;
    const int qcol = h * HDIM;
    const float scale = 0.125f;

    const uint32_t qoff2 = (uint32_t)(((wid * 16) + ((lane >> 3) & 1) * 8 + (lane & 7)) * FLD
                                      + (lane >> 4) * 8) * 2;
    const uint32_t koff2 = (uint32_t)(((lane >> 4) * 8 + (lane & 7)) * FLD
                                      + ((lane >> 3) & 1) * 8) * 2;
    const uint32_t voff2 = (uint32_t)((((lane >> 3) & 1) * 8 + (lane & 7)) * FLD
                                      + (lane >> 4) * 8) * 2;

    #pragma unroll
    for (int i = 0; i < 4; i++) {
        int p = tid + i * 256;
        int r = p >> 3, c8 = (p & 7) * 8;
        size_t src = (size_t)(qb * 128 + r) * N3 + qcol + c8;
        *reinterpret_cast<uint4*>(&smf[OQH + r * FLD + c8]) =
            *reinterpret_cast<const uint4*>(qh_g + src);
        *reinterpret_cast<uint4*>(&smf[OQL + r * FLD + c8]) =
            *reinterpret_cast<const uint4*>(ql_g + src);
    }

    float O[8][4];
    #pragma unroll
    for (int nt = 0; nt < 8; nt++)
        #pragma unroll
        for (int e = 0; e < 4; e++) O[nt][e] = 0.0f;
    float m0r = -1e30f, m1r = -1e30f, l0r = 0.0f, l1r = 0.0f;

    const uint32_t qbh = sb + OQH * 2 + qoff2;
    const uint32_t qbl = sb + OQL * 2 + qoff2;
    const uint32_t kbh = sb + OKH * 2 + koff2;
    const uint32_t kbl = sb + OKL * 2 + koff2;
    const uint32_t vbh = sb + OVH * 2 + voff2;
    const uint32_t vbl = sb + OVL * 2 + voff2;

    const int nkt = 2 * qb + 2;
    for (int kb = 0; kb < nkt; kb++) {
        __syncthreads();
        #pragma unroll
        for (int i = 0; i < 2; i++) {
            int p = tid + i * 256;
            int r = p >> 3, c8 = (p & 7) * 8;
            size_t ksrc = (size_t)(kb * 64 + r) * N3 + DMODEL + qcol + c8;
            size_t vsrc = ksrc + DMODEL;
            *reinterpret_cast<uint4*>(&smf[OKH + r * FLD + c8]) =
                *reinterpret_cast<const uint4*>(qh_g + ksrc);
            *reinterpret_cast<uint4*>(&smf[OKL + r * FLD + c8]) =
                *reinterpret_cast<const uint4*>(ql_g + ksrc);
            *reinterpret_cast<uint4*>(&smf[OVH + r * FLD + c8]) =
                *reinterpret_cast<const uint4*>(qh_g + vsrc);
            *reinterpret_cast<uint4*>(&smf[OVL + r * FLD + c8]) =
                *reinterpret_cast<const uint4*>(ql_g + vsrc);
        }
        __syncthreads();

        float S[8][4];
        #pragma unroll
        for (int nt = 0; nt < 8; nt++)
            #pragma unroll
            for (int e = 0; e < 4; e++) S[nt][e] = 0.0f;

        #pragma unroll
        for (int ks = 0; ks < 4; ks++) {
            uint32_t qh4[4], ql4[4];
            ldm_x4(qh4, qbh + ks * 32);
            ldm_x4(ql4, qbl + ks * 32);
            #pragma unroll
            for (int ntp = 0; ntp < 4; ntp++) {
                uint32_t kh4[4], kl4[4];
                ldm_x4(kh4, kbh + ntp * 2304 + ks * 32);
                ldm_x4(kl4, kbl + ntp * 2304 + ks * 32);
                // interleaved across the two accumulators (distance 2)
                mma_bf16(S[2 * ntp],     qh4, &kh4[0]);
                mma_bf16(S[2 * ntp + 1], qh4, &kh4[2]);
                mma_bf16(S[2 * ntp],     qh4, &kl4[0]);
                mma_bf16(S[2 * ntp + 1], qh4, &kl4[2]);
                mma_bf16(S[2 * ntp],     ql4, &kh4[0]);
                mma_bf16(S[2 * ntp + 1], ql4, &kh4[2]);
            }
        }

        #pragma unroll
        for (int nt = 0; nt < 8; nt++) {
            S[nt][0] *= scale; S[nt][1] *= scale;
            S[nt][2] *= scale; S[nt][3] *= scale;
        }
        if (kb >= 2 * qb) {
            int row0 = qb * 128 + wid * 16 + g;
            int row1 = row0 + 8;
            #pragma unroll
            for (int nt = 0; nt < 8; nt++) {
                int c = kb * 64 + nt * 8 + 2 * q4;
                if (c     > row0) S[nt][0] = -1e30f;
                if (c + 1 > row0) S[nt][1] = -1e30f;
                if (c     > row1) S[nt][2] = -1e30f;
                if (c + 1 > row1) S[nt][3] = -1e30f;
            }
        }

        float mx0 = -1e30f, mx1 = -1e30f;
        #pragma unroll
        for (int nt = 0; nt < 8; nt++) {
            mx0 = fmaxf(mx0, fmaxf(S[nt][0], S[nt][1]));
            mx1 = fmaxf(mx1, fmaxf(S[nt][2], S[nt][3]));
        }
        mx0 = fmaxf(mx0, __shfl_xor_sync(0xffffffffu, mx0, 1));
        mx0 = fmaxf(mx0, __shfl_xor_sync(0xffffffffu, mx0, 2));
        mx1 = fmaxf(mx1, __shfl_xor_sync(0xffffffffu, mx1, 1));
        mx1 = fmaxf(mx1, __shfl_xor_sync(0xffffffffu, mx1, 2));
        float mn0 = fmaxf(m0r, mx0), mn1 = fmaxf(m1r, mx1);
        float al0 = __expf(m0r - mn0), al1 = __expf(m1r - mn1);
        float rs0 = 0.0f, rs1 = 0.0f;
        #pragma unroll
        for (int nt = 0; nt < 8; nt++) {
            S[nt][0] = __expf(S[nt][0] - mn0);
            S[nt][1] = __expf(S[nt][1] - mn0);
            S[nt][2] = __expf(S[nt][2] - mn1);
            S[nt][3] = __expf(S[nt][3] - mn1);
            rs0 += S[nt][0] + S[nt][1];
            rs1 += S[nt][2] + S[nt][3];
        }
        rs0 += __shfl_xor_sync(0xffffffffu, rs0, 1);
        rs0 += __shfl_xor_sync(0xffffffffu, rs0, 2);
        rs1 += __shfl_xor_sync(0xffffffffu, rs1, 1);
        rs1 += __shfl_xor_sync(0xffffffffu, rs1, 2);
        l0r = l0r * al0 + rs0;
        l1r = l1r * al1 + rs1;
        m0r = mn0; m1r = mn1;
        #pragma unroll
        for (int nt = 0; nt < 8; nt++) {
            O[nt][0] *= al0; O[nt][1] *= al0;
            O[nt][2] *= al1; O[nt][3] *= al1;
        }

        #pragma unroll
        for (int ks = 0; ks < 4; ks++) {
            uint32_t ph[4], pl[4];
            pack_pair(S[2 * ks][0],     S[2 * ks][1],     ph[0], pl[0]);
            pack_pair(S[2 * ks][2],     S[2 * ks][3],     ph[1], pl[1]);
            pack_pair(S[2 * ks + 1][0], S[2 * ks + 1][1], ph[2], pl[2]);
            pack_pair(S[2 * ks + 1][2], S[2 * ks + 1][3], ph[3], pl[3]);
            #pragma unroll
            for (int ntp = 0; ntp < 4; ntp++) {
                uint32_t vh4[4], vl4[4];
                ldm_x4_t(vh4, vbh + ks * 2304 + ntp * 32);
                ldm_x4_t(vl4, vbl + ks * 2304 + ntp * 32);
                // interleaved across the two accumulators (distance 2)
                mma_bf16(O[2 * ntp],     ph, &vh4[0]);
                mma_bf16(O[2 * ntp + 1], ph, &vh4[2]);
                mma_bf16(O[2 * ntp],     ph, &vl4[0]);
                mma_bf16(O[2 * ntp + 1], ph, &vl4[2]);
                mma_bf16(O[2 * ntp],     pl, &vh4[0]);
                mma_bf16(O[2 * ntp + 1], pl, &vh4[2]);
            }
        }
    }

    float inv0 = 1.0f / l0r, inv1 = 1.0f / l1r;
    int row0 = qb * 128 + wid * 16 + g;
    int row1 = row0 + 8;
    #pragma unroll
    for (int nt = 0; nt < 8; nt++) {
        int col = qcol + nt * 8 + 2 * q4;
        float2 o0 = {O[nt][0] * inv0, O[nt][1] * inv0};
        float2 o1 = {O[nt][2] * inv1, O[nt][3] * inv1};
        *reinterpret_cast<float2*>(outp + (size_t)row0 * DMODEL + col) = o0;
        *reinterpret_cast<float2*>(outp + (size_t)row1 * DMODEL + col) = o1;
    }
}

// ---------------------------------------------------------------------------
// Launch
// ---------------------------------------------------------------------------
extern "C" void kernel_launch(void* const* d_in, const int* in_sizes, int n_in,
                              void* d_out, int out_size) {
    const float* x      = (const float*)d_in[0];
    const float* w_qkv  = (const float*)d_in[1];
    const float* b_qkv  = (const float*)d_in[2];
    const float* w_proj = (const float*)d_in[3];
    const float* b_proj = (const float*)d_in[4];
    float* out = (float*)d_out;

    float *qkv, *attn;
    __nv_bfloat16 *qkvh, *qkvl, *xhi, *xlo, *ahi, *alo, *wqh, *wql, *wph, *wpl;
    cudaGetSymbolAddress((void**)&qkv, g_qkv);
    cudaGetSymbolAddress((void**)&attn, g_attn);
    cudaGetSymbolAddress((void**)&qkvh, g_qkvh);
    cudaGetSymbolAddress((void**)&qkvl, g_qkvl);
    cudaGetSymbolAddress((void**)&xhi, g_xhi);
    cudaGetSymbolAddress((void**)&xlo, g_xlo);
    cudaGetSymbolAddress((void**)&ahi, g_ahi);
    cudaGetSymbolAddress((void**)&alo, g_alo);
    cudaGetSymbolAddress((void**)&wqh, g_wqh);
    cudaGetSymbolAddress((void**)&wql, g_wql);
    cudaGetSymbolAddress((void**)&wph, g_wph);
    cudaGetSymbolAddress((void**)&wpl, g_wpl);

    cudaFuncSetAttribute(flash_bf16_kernel,
                         cudaFuncAttributeMaxDynamicSharedMemorySize, FLASH_SMEM);

    // Prep: split x; split+transpose weights
    split_kernel<<<S_LEN * DMODEL / 1024, 256>>>(x, xhi, xlo);
    splitT_kernel<<<dim3(N3 / 32, DMODEL / 32), dim3(32, 8)>>>(w_qkv, wqh, wql, DMODEL, N3);
    splitT_kernel<<<dim3(DMODEL / 32, DMODEL / 32), dim3(32, 8)>>>(w_proj, wph, wpl, DMODEL, DMODEL);

    // 1) QKV projection (fp32 out)
    gemm_bf16_kernel<<<dim3(N3 / 128, S_LEN / 128), 256>>>(
        xhi, xlo, wqh, wql, b_qkv, qkv, S_LEN, N3, DMODEL);

    // 1b) Split qkv to bf16 hi/lo once
    split_kernel<<<S_LEN * N3 / 1024, 256>>>(qkv, qkvh, qkvl);

    // 2) Causal flash attention (reads pre-split bf16)
    flash_bf16_kernel<<<dim3(S_LEN / 128, NHEAD), 256, FLASH_SMEM>>>(qkvh, qkvl, attn);

    // 3) Output projection
    split_kernel<<<S_LEN * DMODEL / 1024, 256>>>(attn, ahi, alo);
    gemm_bf16_kernel<<<dim3(DMODEL / 128, S_LEN / 128), 256>>>(
        ahi, alo, wph, wpl, b_proj, out, S_LEN, DMODEL, DMODEL);
}